// round 10
// baseline (speedup 1.0000x reference)
#include <cuda_runtime.h>
#include <cuda_bf16.h>
#include <math.h>

#define T_LEN 1024
#define K_LEN 1024
#define H_DIM 256
#define E_DIM 64
#define TOPIC 100
#define EXLEN 768
#define GRU_IN 201   // 2*TOPIC + 1
#define TOPK 64

// ---------------- device scratch ----------------
__device__ float g_v[TOPIC];
__device__ float g_kn[E_DIM];
__device__ float g_betaall[T_LEN];
__device__ float g_adot[K_LEN];
__device__ float g_beta[TOPK];
__device__ int   g_topidx[TOPK];
__device__ float g_alpha[K_LEN];
__device__ float g_u[3 * H_DIM];
__device__ float g_hkp[H_DIM];
__device__ float g_gh[K_LEN * 3 * H_DIM];

__device__ __forceinline__ unsigned f2tf32(float f) {
    unsigned r;
    asm("cvt.rna.tf32.f32 %0, %1;" : "=r"(r) : "f"(f));
    return r;
}

// ---------------- K1: v = W_resize@ex_e + b ; kn = Wk@co_e + bk ----------
__global__ void k1_embed(const float* __restrict__ W_resize,
                         const float* __restrict__ b_resize,
                         const float* __restrict__ ex_e,
                         const float* __restrict__ Wk,
                         const float* __restrict__ bk,
                         const float* __restrict__ co_e) {
    int lane = threadIdx.x & 31;
    int gw = blockIdx.x * 8 + (threadIdx.x >> 5);
    if (blockIdx.x == 0 && threadIdx.x < H_DIM) g_hkp[threadIdx.x] = 0.f;
    if (gw < TOPIC) {
        const float* wr = W_resize + gw * EXLEN;
        float p = 0.f;
        for (int i = lane; i < EXLEN; i += 32) p += wr[i] * ex_e[i];
        #pragma unroll
        for (int o = 16; o; o >>= 1) p += __shfl_xor_sync(0xffffffffu, p, o);
        if (lane == 0) g_v[gw] = p + b_resize[gw];
    } else if (gw < TOPIC + E_DIM) {
        int row = gw - TOPIC;
        const float* wr = Wk + row * K_LEN;
        float p = 0.f;
        for (int i = lane; i < K_LEN; i += 32) p += wr[i] * co_e[i];
        #pragma unroll
        for (int o = 16; o; o >>= 1) p += __shfl_xor_sync(0xffffffffu, p, o);
        if (lane == 0) g_kn[row] = p + bk[row];
    }
}

// ---- K2: dots (352 blocks) + independent tf32 GEMM (96 blocks) ----------
#define DOT_BLOCKS 352
#define GBM 128
#define GBN 64

__device__ __forceinline__ void mma_tf32(float* c, const unsigned* a, const unsigned* b) {
    asm volatile(
        "mma.sync.aligned.m16n8k8.row.col.f32.tf32.tf32.f32 "
        "{%0,%1,%2,%3}, {%4,%5,%6,%7}, {%8,%9}, {%0,%1,%2,%3};\n"
        : "+f"(c[0]), "+f"(c[1]), "+f"(c[2]), "+f"(c[3])
        : "r"(a[0]), "r"(a[1]), "r"(a[2]), "r"(a[3]), "r"(b[0]), "r"(b[1]));
}

__global__ void k2_dots_gemm(const float* __restrict__ vs,
                             const float* __restrict__ km,
                             const float* __restrict__ W_ih,
                             const float* __restrict__ s_ptr,
                             const float* __restrict__ A,   // h0 [1024,256]
                             const float* __restrict__ B) { // W_hh [768,256]
    __shared__ struct { unsigned As[GBM][36]; unsigned Bs[GBN][36]; } smg;
    int tid = threadIdx.x;

    if (blockIdx.x < DOT_BLOCKS) {
        int lane = tid & 31;
        int gw = blockIdx.x * 8 + (tid >> 5);
        if (gw < T_LEN) {
            const float* vr = vs + gw * TOPIC;
            float p = 0.f;
            for (int i = lane; i < TOPIC; i += 32) p += vr[i] * g_v[i];
            #pragma unroll
            for (int o = 16; o; o >>= 1) p += __shfl_xor_sync(0xffffffffu, p, o);
            if (lane == 0) g_betaall[gw] = p;
        } else if (gw < 2 * T_LEN) {
            int row = gw - T_LEN;
            const float* kr = km + row * E_DIM;
            float p = 0.f;
            for (int i = lane; i < E_DIM; i += 32) p += kr[i] * g_kn[i];
            #pragma unroll
            for (int o = 16; o; o >>= 1) p += __shfl_xor_sync(0xffffffffu, p, o);
            if (lane == 0) g_adot[row] = p;
        } else if (gw < 2 * T_LEN + 3 * H_DIM) {
            int row = gw - 2 * T_LEN;
            float s = s_ptr[0];
            float mask = (s >= 0.5f) ? 1.f : 0.f;
            const float* wr = W_ih + row * GRU_IN;
            float p = 0.f;
            for (int i = lane; i < GRU_IN; i += 32) {
                float xv = (i < TOPIC) ? g_v[i] * mask
                         : (i < 2 * TOPIC) ? g_v[i - TOPIC] * (1.f - mask) : s;
                p += wr[i] * xv;
            }
            #pragma unroll
            for (int o = 16; o; o >>= 1) p += __shfl_xor_sync(0xffffffffu, p, o);
            if (lane == 0) g_u[row] = p;
        }
    } else {
        // ---- tf32 MMA GEMM ----
        int bi = blockIdx.x - DOT_BLOCKS;     // 0..95
        int nblk = bi % 12;
        int mblk = bi / 12;
        int m0 = mblk * GBM, n0 = nblk * GBN;
        int lane = tid & 31, wid = tid >> 5;
        int wm = (wid & 3) * 32, wn = (wid >> 2) * 32;
        int g = lane >> 2, tg = lane & 3;
        int lr = tid >> 3;            // 0..31
        int lc4 = (tid & 7) * 4;      // 0,4..28

        float c[2][4][4];
        #pragma unroll
        for (int mt = 0; mt < 2; mt++)
            #pragma unroll
            for (int nt = 0; nt < 4; nt++)
                #pragma unroll
                for (int i = 0; i < 4; i++) c[mt][nt][i] = 0.f;

        for (int kt = 0; kt < H_DIM; kt += 32) {
            float4 a4[4], b4[2];
            #pragma unroll
            for (int i = 0; i < 4; i++)
                a4[i] = *(const float4*)(A + (size_t)(m0 + lr + 32 * i) * H_DIM + kt + lc4);
            #pragma unroll
            for (int i = 0; i < 2; i++)
                b4[i] = *(const float4*)(B + (size_t)(n0 + lr + 32 * i) * H_DIM + kt + lc4);
            __syncthreads();
            #pragma unroll
            for (int i = 0; i < 4; i++) {
                smg.As[lr + 32 * i][lc4 + 0] = f2tf32(a4[i].x);
                smg.As[lr + 32 * i][lc4 + 1] = f2tf32(a4[i].y);
                smg.As[lr + 32 * i][lc4 + 2] = f2tf32(a4[i].z);
                smg.As[lr + 32 * i][lc4 + 3] = f2tf32(a4[i].w);
            }
            #pragma unroll
            for (int i = 0; i < 2; i++) {
                smg.Bs[lr + 32 * i][lc4 + 0] = f2tf32(b4[i].x);
                smg.Bs[lr + 32 * i][lc4 + 1] = f2tf32(b4[i].y);
                smg.Bs[lr + 32 * i][lc4 + 2] = f2tf32(b4[i].z);
                smg.Bs[lr + 32 * i][lc4 + 3] = f2tf32(b4[i].w);
            }
            __syncthreads();
            #pragma unroll
            for (int ks = 0; ks < 32; ks += 8) {
                unsigned afr[2][4], bfr[4][2];
                #pragma unroll
                for (int mt = 0; mt < 2; mt++) {
                    int r0 = wm + mt * 16 + g;
                    afr[mt][0] = smg.As[r0][ks + tg];
                    afr[mt][1] = smg.As[r0 + 8][ks + tg];
                    afr[mt][2] = smg.As[r0][ks + tg + 4];
                    afr[mt][3] = smg.As[r0 + 8][ks + tg + 4];
                }
                #pragma unroll
                for (int nt = 0; nt < 4; nt++) {
                    int r0 = wn + nt * 8 + g;
                    bfr[nt][0] = smg.Bs[r0][ks + tg];
                    bfr[nt][1] = smg.Bs[r0][ks + tg + 4];
                }
                #pragma unroll
                for (int mt = 0; mt < 2; mt++)
                    #pragma unroll
                    for (int nt = 0; nt < 4; nt++)
                        mma_tf32(c[mt][nt], afr[mt], bfr[nt]);
            }
        }
        #pragma unroll
        for (int mt = 0; mt < 2; mt++) {
            int row = m0 + wm + mt * 16 + g;
            #pragma unroll
            for (int nt = 0; nt < 4; nt++) {
                int col = n0 + wn + nt * 8 + 2 * tg;
                *(float2*)(g_gh + (size_t)row * (3 * H_DIM) + col)
                    = make_float2(c[mt][nt][0], c[mt][nt][1]);
                *(float2*)(g_gh + (size_t)(row + 8) * (3 * H_DIM) + col)
                    = make_float2(c[mt][nt][2], c[mt][nt][3]);
            }
        }
    }
}

// ---------------- K3: hybrid bitonic top-k + softmaxes -------------------
__global__ void k3_select() {
    __shared__ unsigned long long skey[T_LEN];
    __shared__ float sv2[TOPK];
    __shared__ int   si2[TOPK];
    __shared__ float sred[32];
    int tid = threadIdx.x, lane = tid & 31, wid = tid >> 5;

    float bv = g_betaall[tid];
    unsigned u = __float_as_uint(bv);
    u = (u & 0x80000000u) ? ~u : (u | 0x80000000u);
    unsigned long long key = ((unsigned long long)u << 32) | (unsigned)tid;

    for (int k = 2; k <= T_LEN; k <<= 1) {
        for (int j = k >> 1; j > 0; j >>= 1) {
            bool keepmax = (((tid & k) == 0) == ((tid & j) == 0));
            unsigned long long p;
            if (j >= 32) {
                skey[tid] = key;
                __syncthreads();
                p = skey[tid ^ j];
                __syncthreads();
            } else {
                p = __shfl_xor_sync(0xffffffffu, key, j);
            }
            unsigned long long hi = (key > p) ? key : p;
            unsigned long long lo = (key > p) ? p : key;
            key = keepmax ? hi : lo;
        }
    }

    if (tid < TOPK) {
        unsigned su = (unsigned)(key >> 32);
        float val = __uint_as_float((su & 0x80000000u) ? (su ^ 0x80000000u) : ~su);
        sv2[tid] = val;
        si2[tid] = (int)(key & 0xffffffffu);
    }
    __syncthreads();

    if (tid < 32) {
        float m  = sv2[0];
        float e0 = __expf(sv2[lane] - m);
        float e1 = __expf(sv2[lane + 32] - m);
        float sm = e0 + e1;
        #pragma unroll
        for (int o = 16; o; o >>= 1) sm += __shfl_xor_sync(0xffffffffu, sm, o);
        g_beta[lane]        = e0 / sm;
        g_beta[lane + 32]   = e1 / sm;
        g_topidx[lane]      = si2[lane];
        g_topidx[lane + 32] = si2[lane + 32];
    }

    float dv = g_adot[tid];
    float wmax = dv;
    #pragma unroll
    for (int o = 16; o; o >>= 1) wmax = fmaxf(wmax, __shfl_xor_sync(0xffffffffu, wmax, o));
    if (lane == 0) sred[wid] = wmax;
    __syncthreads();
    if (tid < 32) {
        float x = sred[lane];
        #pragma unroll
        for (int o = 16; o; o >>= 1) x = fmaxf(x, __shfl_xor_sync(0xffffffffu, x, o));
        if (lane == 0) sred[0] = x;
    }
    __syncthreads();
    float mx = sred[0];
    __syncthreads();
    float ev = __expf(dv - mx);
    float ws = ev;
    #pragma unroll
    for (int o = 16; o; o >>= 1) ws += __shfl_xor_sync(0xffffffffu, ws, o);
    if (lane == 0) sred[wid] = ws;
    __syncthreads();
    if (tid < 32) {
        float x = sred[lane];
        #pragma unroll
        for (int o = 16; o; o >>= 1) x += __shfl_xor_sync(0xffffffffu, x, o);
        if (lane == 0) sred[0] = x;
    }
    __syncthreads();
    g_alpha[tid] = ev / sred[0];
}

// ---------------- K4: gather, deep-MLP (1024 blocks x 64-row chunks) -----
// Each thread: 16 independent LDG.128s front-batched into registers, then
// accumulate. hkp[hh] += beta_j * sum_kk alpha_kk * hs[idx_j, kk, hh].
__global__ void k4_gather(const float* __restrict__ hs) {
    __shared__ float  sal[64];
    __shared__ float4 sacc[256];
    int bid = blockIdx.x;                    // 0..1023
    int j = bid & 63;
    int kk0 = (bid >> 6) * 64;               // 16 chunks of 64 rows
    int tid = threadIdx.x;
    if (tid < 64) sal[tid] = g_alpha[kk0 + tid];
    __syncthreads();

    int slice = g_topidx[j];
    const float4* base = (const float4*)hs
                       + (size_t)slice * (K_LEN * (H_DIM / 4))
                       + (size_t)kk0 * (H_DIM / 4);
    int t4 = tid & 63;    // float4 column
    int rg = tid >> 6;    // 0..3 row group

    // front-batched independent loads (deep MLP)
    float4 v[16];
    #pragma unroll
    for (int i = 0; i < 16; i++)
        v[i] = base[(rg + 4 * i) * (H_DIM / 4) + t4];

    float4 acc0 = make_float4(0.f, 0.f, 0.f, 0.f);
    float4 acc1 = make_float4(0.f, 0.f, 0.f, 0.f);
    #pragma unroll
    for (int i = 0; i < 16; i += 2) {
        float a0 = sal[rg + 4 * i];
        float a1 = sal[rg + 4 * (i + 1)];
        acc0.x = fmaf(a0, v[i].x, acc0.x);     acc0.y = fmaf(a0, v[i].y, acc0.y);
        acc0.z = fmaf(a0, v[i].z, acc0.z);     acc0.w = fmaf(a0, v[i].w, acc0.w);
        acc1.x = fmaf(a1, v[i + 1].x, acc1.x); acc1.y = fmaf(a1, v[i + 1].y, acc1.y);
        acc1.z = fmaf(a1, v[i + 1].z, acc1.z); acc1.w = fmaf(a1, v[i + 1].w, acc1.w);
    }
    float4 acc = make_float4(acc0.x + acc1.x, acc0.y + acc1.y,
                             acc0.z + acc1.z, acc0.w + acc1.w);
    sacc[tid] = acc;
    __syncthreads();
    if (tid < 64) {
        float4 a0 = sacc[tid], a1 = sacc[64 + tid];
        float4 a2 = sacc[128 + tid], a3 = sacc[192 + tid];
        float b = g_beta[j];
        atomicAdd(&g_hkp[tid * 4 + 0], b * (a0.x + a1.x + a2.x + a3.x));
        atomicAdd(&g_hkp[tid * 4 + 1], b * (a0.y + a1.y + a2.y + a3.y));
        atomicAdd(&g_hkp[tid * 4 + 2], b * (a0.z + a1.z + a2.z + a3.z));
        atomicAdd(&g_hkp[tid * 4 + 3], b * (a0.w + a1.w + a2.w + a3.w));
    }
}

// ---------------- K5: GRU gates + h_new + predict_score ------------------
__global__ void k5_gru(const float* __restrict__ h0,
                       const float* __restrict__ b_ih,
                       const float* __restrict__ b_hh,
                       const float* __restrict__ W_score,
                       const float* __restrict__ b_score,
                       float* __restrict__ out) {
    int kk = blockIdx.x;
    int hh = threadIdx.x;
    float a = g_alpha[kk];
    const float* gh = g_gh + (size_t)kk * (3 * H_DIM);

    float gir = fmaf(a, g_u[hh],             b_ih[hh]);
    float giz = fmaf(a, g_u[H_DIM + hh],     b_ih[H_DIM + hh]);
    float gin = fmaf(a, g_u[2 * H_DIM + hh], b_ih[2 * H_DIM + hh]);
    float ghr = gh[hh]             + b_hh[hh];
    float ghz = gh[H_DIM + hh]     + b_hh[H_DIM + hh];
    float ghn = gh[2 * H_DIM + hh] + b_hh[2 * H_DIM + hh];

    float r = 1.f / (1.f + __expf(-(gir + ghr)));
    float z = 1.f / (1.f + __expf(-(giz + ghz)));
    float n = tanhf(gin + r * ghn);
    float h0v = h0[(size_t)kk * H_DIM + hh];
    out[1 + (size_t)kk * H_DIM + hh] = (1.f - z) * n + z * h0v;

    if (kk == 0 && hh < 32) {
        float p = 0.f;
        for (int i = hh; i < TOPIC + H_DIM; i += 32) {
            float pv = (i < TOPIC) ? g_v[i] : g_hkp[i - TOPIC];
            p += W_score[i] * pv;
        }
        #pragma unroll
        for (int o = 16; o; o >>= 1) p += __shfl_xor_sync(0xffffffffu, p, o);
        if (hh == 0) out[0] = p + b_score[0];
    }
}

// ---------------------------------------------------------------------------
extern "C" void kernel_launch(void* const* d_in, const int* in_sizes, int n_in,
                              void* d_out, int out_size) {
    const float* co_e     = (const float*)d_in[0];
    const float* ex_e     = (const float*)d_in[1];
    const float* s        = (const float*)d_in[2];
    const float* h        = (const float*)d_in[3];
    const float* vs       = (const float*)d_in[4];
    const float* hs       = (const float*)d_in[5];
    const float* W_resize = (const float*)d_in[6];
    const float* b_resize = (const float*)d_in[7];
    const float* Wk       = (const float*)d_in[8];
    const float* bk       = (const float*)d_in[9];
    const float* km       = (const float*)d_in[10];
    const float* W_score  = (const float*)d_in[11];
    const float* b_score  = (const float*)d_in[12];
    const float* W_ih     = (const float*)d_in[13];
    const float* W_hh     = (const float*)d_in[14];
    const float* b_ih     = (const float*)d_in[15];
    const float* b_hh     = (const float*)d_in[16];
    float* out = (float*)d_out;

    k1_embed    <<<21, 256>>>(W_resize, b_resize, ex_e, Wk, bk, co_e);
    k2_dots_gemm<<<DOT_BLOCKS + 96, 256>>>(vs, km, W_ih, s, h, W_hh);
    k3_select   <<<1, 1024>>>();
    k4_gather   <<<1024, 256>>>(hs);
    k5_gru      <<<K_LEN, 256>>>(h, b_ih, b_hh, W_score, b_score, out);
}

// round 11
// speedup vs baseline: 1.4623x; 1.4623x over previous
#include <cuda_runtime.h>
#include <cuda_bf16.h>
#include <math.h>
#include <stdint.h>

#define T_LEN 1024
#define K_LEN 1024
#define H_DIM 256
#define E_DIM 64
#define TOPIC 100
#define EXLEN 768
#define GRU_IN 201   // 2*TOPIC + 1
#define TOPK 64

// ---------------- device scratch ----------------
__device__ float g_v[TOPIC];
__device__ float g_kn[E_DIM];
__device__ float g_betaall[T_LEN];
__device__ float g_adot[K_LEN];
__device__ float g_beta[TOPK];
__device__ int   g_topidx[TOPK];
__device__ float g_alpha[K_LEN];
__device__ float g_u[3 * H_DIM];
__device__ float g_hkp[H_DIM];
__device__ float g_gh[K_LEN * 3 * H_DIM];

__device__ __forceinline__ unsigned f2tf32(float f) {
    unsigned r;
    asm("cvt.rna.tf32.f32 %0, %1;" : "=r"(r) : "f"(f));
    return r;
}

__device__ __forceinline__ uint32_t smem_u32(const void* p) {
    uint32_t a;
    asm("{ .reg .u64 t; cvta.to.shared.u64 t, %1; cvt.u32.u64 %0, t; }"
        : "=r"(a) : "l"(p));
    return a;
}

// ---------------- K1: v = W_resize@ex_e + b ; kn = Wk@co_e + bk ----------
__global__ void k1_embed(const float* __restrict__ W_resize,
                         const float* __restrict__ b_resize,
                         const float* __restrict__ ex_e,
                         const float* __restrict__ Wk,
                         const float* __restrict__ bk,
                         const float* __restrict__ co_e) {
    int lane = threadIdx.x & 31;
    int gw = blockIdx.x * 8 + (threadIdx.x >> 5);
    if (blockIdx.x == 0 && threadIdx.x < H_DIM) g_hkp[threadIdx.x] = 0.f;
    if (gw < TOPIC) {
        const float* wr = W_resize + gw * EXLEN;
        float p = 0.f;
        for (int i = lane; i < EXLEN; i += 32) p += wr[i] * ex_e[i];
        #pragma unroll
        for (int o = 16; o; o >>= 1) p += __shfl_xor_sync(0xffffffffu, p, o);
        if (lane == 0) g_v[gw] = p + b_resize[gw];
    } else if (gw < TOPIC + E_DIM) {
        int row = gw - TOPIC;
        const float* wr = Wk + row * K_LEN;
        float p = 0.f;
        for (int i = lane; i < K_LEN; i += 32) p += wr[i] * co_e[i];
        #pragma unroll
        for (int o = 16; o; o >>= 1) p += __shfl_xor_sync(0xffffffffu, p, o);
        if (lane == 0) g_kn[row] = p + bk[row];
    }
}

// ---- K2: dots (352 blocks) + independent tf32 GEMM (96 blocks) ----------
#define DOT_BLOCKS 352
#define GBM 128
#define GBN 64

__device__ __forceinline__ void mma_tf32(float* c, const unsigned* a, const unsigned* b) {
    asm volatile(
        "mma.sync.aligned.m16n8k8.row.col.f32.tf32.tf32.f32 "
        "{%0,%1,%2,%3}, {%4,%5,%6,%7}, {%8,%9}, {%0,%1,%2,%3};\n"
        : "+f"(c[0]), "+f"(c[1]), "+f"(c[2]), "+f"(c[3])
        : "r"(a[0]), "r"(a[1]), "r"(a[2]), "r"(a[3]), "r"(b[0]), "r"(b[1]));
}

__global__ void k2_dots_gemm(const float* __restrict__ vs,
                             const float* __restrict__ km,
                             const float* __restrict__ W_ih,
                             const float* __restrict__ s_ptr,
                             const float* __restrict__ A,   // h0 [1024,256]
                             const float* __restrict__ B) { // W_hh [768,256]
    __shared__ struct { unsigned As[GBM][36]; unsigned Bs[GBN][36]; } smg;
    int tid = threadIdx.x;

    if (blockIdx.x < DOT_BLOCKS) {
        int lane = tid & 31;
        int gw = blockIdx.x * 8 + (tid >> 5);
        if (gw < T_LEN) {
            const float* vr = vs + gw * TOPIC;
            float p = 0.f;
            for (int i = lane; i < TOPIC; i += 32) p += vr[i] * g_v[i];
            #pragma unroll
            for (int o = 16; o; o >>= 1) p += __shfl_xor_sync(0xffffffffu, p, o);
            if (lane == 0) g_betaall[gw] = p;
        } else if (gw < 2 * T_LEN) {
            int row = gw - T_LEN;
            const float* kr = km + row * E_DIM;
            float p = 0.f;
            for (int i = lane; i < E_DIM; i += 32) p += kr[i] * g_kn[i];
            #pragma unroll
            for (int o = 16; o; o >>= 1) p += __shfl_xor_sync(0xffffffffu, p, o);
            if (lane == 0) g_adot[row] = p;
        } else if (gw < 2 * T_LEN + 3 * H_DIM) {
            int row = gw - 2 * T_LEN;
            float s = s_ptr[0];
            float mask = (s >= 0.5f) ? 1.f : 0.f;
            const float* wr = W_ih + row * GRU_IN;
            float p = 0.f;
            for (int i = lane; i < GRU_IN; i += 32) {
                float xv = (i < TOPIC) ? g_v[i] * mask
                         : (i < 2 * TOPIC) ? g_v[i - TOPIC] * (1.f - mask) : s;
                p += wr[i] * xv;
            }
            #pragma unroll
            for (int o = 16; o; o >>= 1) p += __shfl_xor_sync(0xffffffffu, p, o);
            if (lane == 0) g_u[row] = p;
        }
    } else {
        // ---- tf32 MMA GEMM ----
        int bi = blockIdx.x - DOT_BLOCKS;     // 0..95
        int nblk = bi % 12;
        int mblk = bi / 12;
        int m0 = mblk * GBM, n0 = nblk * GBN;
        int lane = tid & 31, wid = tid >> 5;
        int wm = (wid & 3) * 32, wn = (wid >> 2) * 32;
        int g = lane >> 2, tg = lane & 3;
        int lr = tid >> 3;            // 0..31
        int lc4 = (tid & 7) * 4;      // 0,4..28

        float c[2][4][4];
        #pragma unroll
        for (int mt = 0; mt < 2; mt++)
            #pragma unroll
            for (int nt = 0; nt < 4; nt++)
                #pragma unroll
                for (int i = 0; i < 4; i++) c[mt][nt][i] = 0.f;

        for (int kt = 0; kt < H_DIM; kt += 32) {
            float4 a4[4], b4[2];
            #pragma unroll
            for (int i = 0; i < 4; i++)
                a4[i] = *(const float4*)(A + (size_t)(m0 + lr + 32 * i) * H_DIM + kt + lc4);
            #pragma unroll
            for (int i = 0; i < 2; i++)
                b4[i] = *(const float4*)(B + (size_t)(n0 + lr + 32 * i) * H_DIM + kt + lc4);
            __syncthreads();
            #pragma unroll
            for (int i = 0; i < 4; i++) {
                smg.As[lr + 32 * i][lc4 + 0] = f2tf32(a4[i].x);
                smg.As[lr + 32 * i][lc4 + 1] = f2tf32(a4[i].y);
                smg.As[lr + 32 * i][lc4 + 2] = f2tf32(a4[i].z);
                smg.As[lr + 32 * i][lc4 + 3] = f2tf32(a4[i].w);
            }
            #pragma unroll
            for (int i = 0; i < 2; i++) {
                smg.Bs[lr + 32 * i][lc4 + 0] = f2tf32(b4[i].x);
                smg.Bs[lr + 32 * i][lc4 + 1] = f2tf32(b4[i].y);
                smg.Bs[lr + 32 * i][lc4 + 2] = f2tf32(b4[i].z);
                smg.Bs[lr + 32 * i][lc4 + 3] = f2tf32(b4[i].w);
            }
            __syncthreads();
            #pragma unroll
            for (int ks = 0; ks < 32; ks += 8) {
                unsigned afr[2][4], bfr[4][2];
                #pragma unroll
                for (int mt = 0; mt < 2; mt++) {
                    int r0 = wm + mt * 16 + g;
                    afr[mt][0] = smg.As[r0][ks + tg];
                    afr[mt][1] = smg.As[r0 + 8][ks + tg];
                    afr[mt][2] = smg.As[r0][ks + tg + 4];
                    afr[mt][3] = smg.As[r0 + 8][ks + tg + 4];
                }
                #pragma unroll
                for (int nt = 0; nt < 4; nt++) {
                    int r0 = wn + nt * 8 + g;
                    bfr[nt][0] = smg.Bs[r0][ks + tg];
                    bfr[nt][1] = smg.Bs[r0][ks + tg + 4];
                }
                #pragma unroll
                for (int mt = 0; mt < 2; mt++)
                    #pragma unroll
                    for (int nt = 0; nt < 4; nt++)
                        mma_tf32(c[mt][nt], afr[mt], bfr[nt]);
            }
        }
        #pragma unroll
        for (int mt = 0; mt < 2; mt++) {
            int row = m0 + wm + mt * 16 + g;
            #pragma unroll
            for (int nt = 0; nt < 4; nt++) {
                int col = n0 + wn + nt * 8 + 2 * tg;
                *(float2*)(g_gh + (size_t)row * (3 * H_DIM) + col)
                    = make_float2(c[mt][nt][0], c[mt][nt][1]);
                *(float2*)(g_gh + (size_t)(row + 8) * (3 * H_DIM) + col)
                    = make_float2(c[mt][nt][2], c[mt][nt][3]);
            }
        }
    }
}

// ---------------- K3: hybrid bitonic top-k + softmaxes -------------------
__global__ void k3_select() {
    __shared__ unsigned long long skey[T_LEN];
    __shared__ float sv2[TOPK];
    __shared__ int   si2[TOPK];
    __shared__ float sred[32];
    int tid = threadIdx.x, lane = tid & 31, wid = tid >> 5;

    float bv = g_betaall[tid];
    unsigned u = __float_as_uint(bv);
    u = (u & 0x80000000u) ? ~u : (u | 0x80000000u);
    unsigned long long key = ((unsigned long long)u << 32) | (unsigned)tid;

    for (int k = 2; k <= T_LEN; k <<= 1) {
        for (int j = k >> 1; j > 0; j >>= 1) {
            bool keepmax = (((tid & k) == 0) == ((tid & j) == 0));
            unsigned long long p;
            if (j >= 32) {
                skey[tid] = key;
                __syncthreads();
                p = skey[tid ^ j];
                __syncthreads();
            } else {
                p = __shfl_xor_sync(0xffffffffu, key, j);
            }
            unsigned long long hi = (key > p) ? key : p;
            unsigned long long lo = (key > p) ? p : key;
            key = keepmax ? hi : lo;
        }
    }

    if (tid < TOPK) {
        unsigned su = (unsigned)(key >> 32);
        float val = __uint_as_float((su & 0x80000000u) ? (su ^ 0x80000000u) : ~su);
        sv2[tid] = val;
        si2[tid] = (int)(key & 0xffffffffu);
    }
    __syncthreads();

    if (tid < 32) {
        float m  = sv2[0];
        float e0 = __expf(sv2[lane] - m);
        float e1 = __expf(sv2[lane + 32] - m);
        float sm = e0 + e1;
        #pragma unroll
        for (int o = 16; o; o >>= 1) sm += __shfl_xor_sync(0xffffffffu, sm, o);
        g_beta[lane]        = e0 / sm;
        g_beta[lane + 32]   = e1 / sm;
        g_topidx[lane]      = si2[lane];
        g_topidx[lane + 32] = si2[lane + 32];
    }

    float dv = g_adot[tid];
    float wmax = dv;
    #pragma unroll
    for (int o = 16; o; o >>= 1) wmax = fmaxf(wmax, __shfl_xor_sync(0xffffffffu, wmax, o));
    if (lane == 0) sred[wid] = wmax;
    __syncthreads();
    if (tid < 32) {
        float x = sred[lane];
        #pragma unroll
        for (int o = 16; o; o >>= 1) x = fmaxf(x, __shfl_xor_sync(0xffffffffu, x, o));
        if (lane == 0) sred[0] = x;
    }
    __syncthreads();
    float mx = sred[0];
    __syncthreads();
    float ev = __expf(dv - mx);
    float ws = ev;
    #pragma unroll
    for (int o = 16; o; o >>= 1) ws += __shfl_xor_sync(0xffffffffu, ws, o);
    if (lane == 0) sred[wid] = ws;
    __syncthreads();
    if (tid < 32) {
        float x = sred[lane];
        #pragma unroll
        for (int o = 16; o; o >>= 1) x += __shfl_xor_sync(0xffffffffu, x, o);
        if (lane == 0) sred[0] = x;
    }
    __syncthreads();
    g_alpha[tid] = ev / sred[0];
}

// ---------------- K4: gather via TMA bulk copy (512 blocks) --------------
// Bypasses the LDG issue floor (~2.3 TB/s chip) with cp.async.bulk (UBLKCP).
// Block (j, chunk): stream 128 contiguous rows (128 KB) of hs[idx_j] through
// a 2-stage x 16KB smem ring, reduce with alpha, atomicAdd beta_j * partial.
#define STAGE_BYTES 16384          // 16 rows x 1 KB
#define STAGE_ROWS  16
#define CHUNK_ROWS  128
#define NITER       (CHUNK_ROWS / STAGE_ROWS)   // 8

__global__ void k4_gather(const float* __restrict__ hs) {
    extern __shared__ __align__(16) char dynsm[];      // 2 x STAGE_BYTES
    __shared__ float sal[CHUNK_ROWS];
    __shared__ float4 sacc[256];
    __shared__ unsigned long long mbar[2];

    int tid = threadIdx.x;
    int bid = blockIdx.x;             // 0..511
    int j = bid & 63;
    int chunk = bid >> 6;             // 0..7
    int kk0 = chunk * CHUNK_ROWS;

    if (tid < CHUNK_ROWS) sal[tid] = g_alpha[kk0 + tid];

    uint32_t mb0 = smem_u32(&mbar[0]);
    uint32_t mb1 = smem_u32(&mbar[1]);
    uint32_t stg_base = smem_u32(dynsm);

    int slice = g_topidx[j];
    const char* src = (const char*)hs
                    + (size_t)slice * (K_LEN * H_DIM * 4)
                    + (size_t)kk0 * (H_DIM * 4);

    if (tid == 0) {
        asm volatile("mbarrier.init.shared.b64 [%0], 1;" :: "r"(mb0) : "memory");
        asm volatile("mbarrier.init.shared.b64 [%0], 1;" :: "r"(mb1) : "memory");
        asm volatile("fence.proxy.async.shared::cta;" ::: "memory");
    }
    __syncthreads();

    // prologue: issue stages for iter 0 and 1
    if (tid == 0) {
        asm volatile("mbarrier.arrive.expect_tx.shared.b64 _, [%0], %1;"
                     :: "r"(mb0), "r"((unsigned)STAGE_BYTES) : "memory");
        asm volatile("cp.async.bulk.shared::cluster.global.mbarrier::complete_tx::bytes "
                     "[%0], [%1], %2, [%3];"
                     :: "r"(stg_base), "l"(src), "r"((unsigned)STAGE_BYTES), "r"(mb0)
                     : "memory");
        asm volatile("mbarrier.arrive.expect_tx.shared.b64 _, [%0], %1;"
                     :: "r"(mb1), "r"((unsigned)STAGE_BYTES) : "memory");
        asm volatile("cp.async.bulk.shared::cluster.global.mbarrier::complete_tx::bytes "
                     "[%0], [%1], %2, [%3];"
                     :: "r"(stg_base + STAGE_BYTES), "l"(src + STAGE_BYTES),
                        "r"((unsigned)STAGE_BYTES), "r"(mb1)
                     : "memory");
    }

    int t4 = tid & 63;     // float4 column within a row
    int rg = tid >> 6;     // 0..3 row group
    float4 acc = make_float4(0.f, 0.f, 0.f, 0.f);

    for (int it = 0; it < NITER; it++) {
        int st = it & 1;
        unsigned par = (unsigned)((it >> 1) & 1);
        uint32_t mb = st ? mb1 : mb0;
        // wait for stage data
        asm volatile(
            "{\n\t.reg .pred P;\n"
            "WL_%=:\n\t"
            "mbarrier.try_wait.parity.shared::cta.b64 P, [%0], %1;\n\t"
            "@!P bra WL_%=;\n\t}"
            :: "r"(mb), "r"(par) : "memory");

        const float4* stg = (const float4*)(dynsm + st * STAGE_BYTES);
        int rbase = it * STAGE_ROWS;
        #pragma unroll
        for (int m = 0; m < 4; m++) {
            int r = rg + 4 * m;                      // row within stage
            float a = sal[rbase + r];
            float4 vv = stg[r * (H_DIM / 4) + t4];
            acc.x = fmaf(a, vv.x, acc.x); acc.y = fmaf(a, vv.y, acc.y);
            acc.z = fmaf(a, vv.z, acc.z); acc.w = fmaf(a, vv.w, acc.w);
        }
        __syncthreads();   // all consumers done before stage reuse
        if (tid == 0 && it + 2 < NITER) {
            const char* nsrc = src + (size_t)(it + 2) * STAGE_BYTES;
            asm volatile("mbarrier.arrive.expect_tx.shared.b64 _, [%0], %1;"
                         :: "r"(mb), "r"((unsigned)STAGE_BYTES) : "memory");
            asm volatile("cp.async.bulk.shared::cluster.global.mbarrier::complete_tx::bytes "
                         "[%0], [%1], %2, [%3];"
                         :: "r"(stg_base + st * STAGE_BYTES), "l"(nsrc),
                            "r"((unsigned)STAGE_BYTES), "r"(mb)
                         : "memory");
        }
    }

    sacc[tid] = acc;
    __syncthreads();
    if (tid < 64) {
        float4 a0 = sacc[tid], a1 = sacc[64 + tid];
        float4 a2 = sacc[128 + tid], a3 = sacc[192 + tid];
        float b = g_beta[j];
        atomicAdd(&g_hkp[tid * 4 + 0], b * (a0.x + a1.x + a2.x + a3.x));
        atomicAdd(&g_hkp[tid * 4 + 1], b * (a0.y + a1.y + a2.y + a3.y));
        atomicAdd(&g_hkp[tid * 4 + 2], b * (a0.z + a1.z + a2.z + a3.z));
        atomicAdd(&g_hkp[tid * 4 + 3], b * (a0.w + a1.w + a2.w + a3.w));
    }
}

// ---------------- K5: GRU gates + h_new + predict_score ------------------
__global__ void k5_gru(const float* __restrict__ h0,
                       const float* __restrict__ b_ih,
                       const float* __restrict__ b_hh,
                       const float* __restrict__ W_score,
                       const float* __restrict__ b_score,
                       float* __restrict__ out) {
    int kk = blockIdx.x;
    int hh = threadIdx.x;
    float a = g_alpha[kk];
    const float* gh = g_gh + (size_t)kk * (3 * H_DIM);

    float gir = fmaf(a, g_u[hh],             b_ih[hh]);
    float giz = fmaf(a, g_u[H_DIM + hh],     b_ih[H_DIM + hh]);
    float gin = fmaf(a, g_u[2 * H_DIM + hh], b_ih[2 * H_DIM + hh]);
    float ghr = gh[hh]             + b_hh[hh];
    float ghz = gh[H_DIM + hh]     + b_hh[H_DIM + hh];
    float ghn = gh[2 * H_DIM + hh] + b_hh[2 * H_DIM + hh];

    float r = 1.f / (1.f + __expf(-(gir + ghr)));
    float z = 1.f / (1.f + __expf(-(giz + ghz)));
    float n = tanhf(gin + r * ghn);
    float h0v = h0[(size_t)kk * H_DIM + hh];
    out[1 + (size_t)kk * H_DIM + hh] = (1.f - z) * n + z * h0v;

    if (kk == 0 && hh < 32) {
        float p = 0.f;
        for (int i = hh; i < TOPIC + H_DIM; i += 32) {
            float pv = (i < TOPIC) ? g_v[i] : g_hkp[i - TOPIC];
            p += W_score[i] * pv;
        }
        #pragma unroll
        for (int o = 16; o; o >>= 1) p += __shfl_xor_sync(0xffffffffu, p, o);
        if (hh == 0) out[0] = p + b_score[0];
    }
}

// ---------------------------------------------------------------------------
extern "C" void kernel_launch(void* const* d_in, const int* in_sizes, int n_in,
                              void* d_out, int out_size) {
    const float* co_e     = (const float*)d_in[0];
    const float* ex_e     = (const float*)d_in[1];
    const float* s        = (const float*)d_in[2];
    const float* h        = (const float*)d_in[3];
    const float* vs       = (const float*)d_in[4];
    const float* hs       = (const float*)d_in[5];
    const float* W_resize = (const float*)d_in[6];
    const float* b_resize = (const float*)d_in[7];
    const float* Wk       = (const float*)d_in[8];
    const float* bk       = (const float*)d_in[9];
    const float* km       = (const float*)d_in[10];
    const float* W_score  = (const float*)d_in[11];
    const float* b_score  = (const float*)d_in[12];
    const float* W_ih     = (const float*)d_in[13];
    const float* W_hh     = (const float*)d_in[14];
    const float* b_ih     = (const float*)d_in[15];
    const float* b_hh     = (const float*)d_in[16];
    float* out = (float*)d_out;

    k1_embed    <<<21, 256>>>(W_resize, b_resize, ex_e, Wk, bk, co_e);
    k2_dots_gemm<<<DOT_BLOCKS + 96, 256>>>(vs, km, W_ih, s, h, W_hh);
    k3_select   <<<1, 1024>>>();
    k4_gather   <<<512, 256, 2 * STAGE_BYTES>>>(hs);
    k5_gru      <<<K_LEN, 256>>>(h, b_ih, b_hh, W_score, b_score, out);
}

// round 12
// speedup vs baseline: 2.3060x; 1.5770x over previous
#include <cuda_runtime.h>
#include <cuda_bf16.h>
#include <math.h>

#define T_LEN 1024
#define K_LEN 1024
#define H_DIM 256
#define E_DIM 64
#define TOPIC 100
#define EXLEN 768
#define GRU_IN 201   // 2*TOPIC + 1
#define TOPK 64

// ---------------- device scratch ----------------
__device__ float g_v[TOPIC];
__device__ float g_kn[E_DIM];
__device__ float g_betaall[T_LEN];
__device__ float g_adot[K_LEN];
__device__ float g_beta[TOPK];
__device__ int   g_topidx[TOPK];
__device__ float g_alpha[K_LEN];
__device__ float g_u[3 * H_DIM];
__device__ float g_score;                 // sum_j beta_j * (W_score[100:356] . partial_j)
__device__ float g_gh[K_LEN * 3 * H_DIM];

__device__ __forceinline__ unsigned f2tf32(float f) {
    unsigned r;
    asm("cvt.rna.tf32.f32 %0, %1;" : "=r"(r) : "f"(f));
    return r;
}

// ---------------- K1: v = W_resize@ex_e + b ; kn = Wk@co_e + bk ----------
__global__ void k1_embed(const float* __restrict__ W_resize,
                         const float* __restrict__ b_resize,
                         const float* __restrict__ ex_e,
                         const float* __restrict__ Wk,
                         const float* __restrict__ bk,
                         const float* __restrict__ co_e) {
    int lane = threadIdx.x & 31;
    int gw = blockIdx.x * 8 + (threadIdx.x >> 5);
    if (blockIdx.x == 0 && threadIdx.x == 0) g_score = 0.f;
    if (gw < TOPIC) {
        const float* wr = W_resize + gw * EXLEN;
        float p = 0.f;
        for (int i = lane; i < EXLEN; i += 32) p += wr[i] * ex_e[i];
        #pragma unroll
        for (int o = 16; o; o >>= 1) p += __shfl_xor_sync(0xffffffffu, p, o);
        if (lane == 0) g_v[gw] = p + b_resize[gw];
    } else if (gw < TOPIC + E_DIM) {
        int row = gw - TOPIC;
        const float* wr = Wk + row * K_LEN;
        float p = 0.f;
        for (int i = lane; i < K_LEN; i += 32) p += wr[i] * co_e[i];
        #pragma unroll
        for (int o = 16; o; o >>= 1) p += __shfl_xor_sync(0xffffffffu, p, o);
        if (lane == 0) g_kn[row] = p + bk[row];
    }
}

// ---- K2: dots (352 blocks) + independent tf32 GEMM (96 blocks) ----------
#define DOT_BLOCKS 352
#define GBM 128
#define GBN 64

__device__ __forceinline__ void mma_tf32(float* c, const unsigned* a, const unsigned* b) {
    asm volatile(
        "mma.sync.aligned.m16n8k8.row.col.f32.tf32.tf32.f32 "
        "{%0,%1,%2,%3}, {%4,%5,%6,%7}, {%8,%9}, {%0,%1,%2,%3};\n"
        : "+f"(c[0]), "+f"(c[1]), "+f"(c[2]), "+f"(c[3])
        : "r"(a[0]), "r"(a[1]), "r"(a[2]), "r"(a[3]), "r"(b[0]), "r"(b[1]));
}

__global__ void k2_dots_gemm(const float* __restrict__ vs,
                             const float* __restrict__ km,
                             const float* __restrict__ W_ih,
                             const float* __restrict__ s_ptr,
                             const float* __restrict__ A,   // h0 [1024,256]
                             const float* __restrict__ B) { // W_hh [768,256]
    __shared__ struct { unsigned As[GBM][36]; unsigned Bs[GBN][36]; } smg;
    int tid = threadIdx.x;

    if (blockIdx.x < DOT_BLOCKS) {
        int lane = tid & 31;
        int gw = blockIdx.x * 8 + (tid >> 5);
        if (gw < T_LEN) {
            const float* vr = vs + gw * TOPIC;
            float p = 0.f;
            for (int i = lane; i < TOPIC; i += 32) p += vr[i] * g_v[i];
            #pragma unroll
            for (int o = 16; o; o >>= 1) p += __shfl_xor_sync(0xffffffffu, p, o);
            if (lane == 0) g_betaall[gw] = p;
        } else if (gw < 2 * T_LEN) {
            int row = gw - T_LEN;
            const float* kr = km + row * E_DIM;
            float p = 0.f;
            for (int i = lane; i < E_DIM; i += 32) p += kr[i] * g_kn[i];
            #pragma unroll
            for (int o = 16; o; o >>= 1) p += __shfl_xor_sync(0xffffffffu, p, o);
            if (lane == 0) g_adot[row] = p;
        } else if (gw < 2 * T_LEN + 3 * H_DIM) {
            int row = gw - 2 * T_LEN;
            float s = s_ptr[0];
            float mask = (s >= 0.5f) ? 1.f : 0.f;
            const float* wr = W_ih + row * GRU_IN;
            float p = 0.f;
            for (int i = lane; i < GRU_IN; i += 32) {
                float xv = (i < TOPIC) ? g_v[i] * mask
                         : (i < 2 * TOPIC) ? g_v[i - TOPIC] * (1.f - mask) : s;
                p += wr[i] * xv;
            }
            #pragma unroll
            for (int o = 16; o; o >>= 1) p += __shfl_xor_sync(0xffffffffu, p, o);
            if (lane == 0) g_u[row] = p;
        }
    } else {
        // ---- tf32 MMA GEMM ----
        int bi = blockIdx.x - DOT_BLOCKS;     // 0..95
        int nblk = bi % 12;
        int mblk = bi / 12;
        int m0 = mblk * GBM, n0 = nblk * GBN;
        int lane = tid & 31, wid = tid >> 5;
        int wm = (wid & 3) * 32, wn = (wid >> 2) * 32;
        int g = lane >> 2, tg = lane & 3;
        int lr = tid >> 3;            // 0..31
        int lc4 = (tid & 7) * 4;      // 0,4..28

        float c[2][4][4];
        #pragma unroll
        for (int mt = 0; mt < 2; mt++)
            #pragma unroll
            for (int nt = 0; nt < 4; nt++)
                #pragma unroll
                for (int i = 0; i < 4; i++) c[mt][nt][i] = 0.f;

        for (int kt = 0; kt < H_DIM; kt += 32) {
            float4 a4[4], b4[2];
            #pragma unroll
            for (int i = 0; i < 4; i++)
                a4[i] = *(const float4*)(A + (size_t)(m0 + lr + 32 * i) * H_DIM + kt + lc4);
            #pragma unroll
            for (int i = 0; i < 2; i++)
                b4[i] = *(const float4*)(B + (size_t)(n0 + lr + 32 * i) * H_DIM + kt + lc4);
            __syncthreads();
            #pragma unroll
            for (int i = 0; i < 4; i++) {
                smg.As[lr + 32 * i][lc4 + 0] = f2tf32(a4[i].x);
                smg.As[lr + 32 * i][lc4 + 1] = f2tf32(a4[i].y);
                smg.As[lr + 32 * i][lc4 + 2] = f2tf32(a4[i].z);
                smg.As[lr + 32 * i][lc4 + 3] = f2tf32(a4[i].w);
            }
            #pragma unroll
            for (int i = 0; i < 2; i++) {
                smg.Bs[lr + 32 * i][lc4 + 0] = f2tf32(b4[i].x);
                smg.Bs[lr + 32 * i][lc4 + 1] = f2tf32(b4[i].y);
                smg.Bs[lr + 32 * i][lc4 + 2] = f2tf32(b4[i].z);
                smg.Bs[lr + 32 * i][lc4 + 3] = f2tf32(b4[i].w);
            }
            __syncthreads();
            #pragma unroll
            for (int ks = 0; ks < 32; ks += 8) {
                unsigned afr[2][4], bfr[4][2];
                #pragma unroll
                for (int mt = 0; mt < 2; mt++) {
                    int r0 = wm + mt * 16 + g;
                    afr[mt][0] = smg.As[r0][ks + tg];
                    afr[mt][1] = smg.As[r0 + 8][ks + tg];
                    afr[mt][2] = smg.As[r0][ks + tg + 4];
                    afr[mt][3] = smg.As[r0 + 8][ks + tg + 4];
                }
                #pragma unroll
                for (int nt = 0; nt < 4; nt++) {
                    int r0 = wn + nt * 8 + g;
                    bfr[nt][0] = smg.Bs[r0][ks + tg];
                    bfr[nt][1] = smg.Bs[r0][ks + tg + 4];
                }
                #pragma unroll
                for (int mt = 0; mt < 2; mt++)
                    #pragma unroll
                    for (int nt = 0; nt < 4; nt++)
                        mma_tf32(c[mt][nt], afr[mt], bfr[nt]);
            }
        }
        #pragma unroll
        for (int mt = 0; mt < 2; mt++) {
            int row = m0 + wm + mt * 16 + g;
            #pragma unroll
            for (int nt = 0; nt < 4; nt++) {
                int col = n0 + wn + nt * 8 + 2 * tg;
                *(float2*)(g_gh + (size_t)row * (3 * H_DIM) + col)
                    = make_float2(c[mt][nt][0], c[mt][nt][1]);
                *(float2*)(g_gh + (size_t)(row + 8) * (3 * H_DIM) + col)
                    = make_float2(c[mt][nt][2], c[mt][nt][3]);
            }
        }
    }
}

// ---------------- K3: hybrid bitonic top-k + softmaxes -------------------
__global__ void k3_select() {
    __shared__ unsigned long long skey[T_LEN];
    __shared__ float sv2[TOPK];
    __shared__ int   si2[TOPK];
    __shared__ float sred[32];
    int tid = threadIdx.x, lane = tid & 31, wid = tid >> 5;

    float bv = g_betaall[tid];
    unsigned u = __float_as_uint(bv);
    u = (u & 0x80000000u) ? ~u : (u | 0x80000000u);
    unsigned long long key = ((unsigned long long)u << 32) | (unsigned)tid;

    for (int k = 2; k <= T_LEN; k <<= 1) {
        for (int j = k >> 1; j > 0; j >>= 1) {
            bool keepmax = (((tid & k) == 0) == ((tid & j) == 0));
            unsigned long long p;
            if (j >= 32) {
                skey[tid] = key;
                __syncthreads();
                p = skey[tid ^ j];
                __syncthreads();
            } else {
                p = __shfl_xor_sync(0xffffffffu, key, j);
            }
            unsigned long long hi = (key > p) ? key : p;
            unsigned long long lo = (key > p) ? p : key;
            key = keepmax ? hi : lo;
        }
    }

    if (tid < TOPK) {
        unsigned su = (unsigned)(key >> 32);
        float val = __uint_as_float((su & 0x80000000u) ? (su ^ 0x80000000u) : ~su);
        sv2[tid] = val;
        si2[tid] = (int)(key & 0xffffffffu);
    }
    __syncthreads();

    if (tid < 32) {
        float m  = sv2[0];
        float e0 = __expf(sv2[lane] - m);
        float e1 = __expf(sv2[lane + 32] - m);
        float sm = e0 + e1;
        #pragma unroll
        for (int o = 16; o; o >>= 1) sm += __shfl_xor_sync(0xffffffffu, sm, o);
        g_beta[lane]        = e0 / sm;
        g_beta[lane + 32]   = e1 / sm;
        g_topidx[lane]      = si2[lane];
        g_topidx[lane + 32] = si2[lane + 32];
    }

    float dv = g_adot[tid];
    float wmax = dv;
    #pragma unroll
    for (int o = 16; o; o >>= 1) wmax = fmaxf(wmax, __shfl_xor_sync(0xffffffffu, wmax, o));
    if (lane == 0) sred[wid] = wmax;
    __syncthreads();
    if (tid < 32) {
        float x = sred[lane];
        #pragma unroll
        for (int o = 16; o; o >>= 1) x = fmaxf(x, __shfl_xor_sync(0xffffffffu, x, o));
        if (lane == 0) sred[0] = x;
    }
    __syncthreads();
    float mx = sred[0];
    __syncthreads();
    float ev = __expf(dv - mx);
    float ws = ev;
    #pragma unroll
    for (int o = 16; o; o >>= 1) ws += __shfl_xor_sync(0xffffffffu, ws, o);
    if (lane == 0) sred[wid] = ws;
    __syncthreads();
    if (tid < 32) {
        float x = sred[lane];
        #pragma unroll
        for (int o = 16; o; o >>= 1) x += __shfl_xor_sync(0xffffffffu, x, o);
        if (lane == 0) sred[0] = x;
    }
    __syncthreads();
    g_alpha[tid] = ev / sred[0];
}

// ---------------- K4: gather (R8 body) + scalar-score epilogue -----------
// partial[hh] = sum_kk alpha_kk * hs[idx_j, kk0+kk, hh]  (per block)
// block contributes ONE atomic: g_score += beta_j * (W_score[100:356].partial)
__global__ void k4_gather(const float* __restrict__ hs,
                          const float* __restrict__ W_score) {
    __shared__ float  sal[128];
    __shared__ float4 sacc[256];
    __shared__ float  swsum[2];
    int g = blockIdx.x;                      // 0..511
    int j = g & 63;
    int kk0 = (g >> 6) * 128;
    int tid = threadIdx.x;
    if (tid < 128) sal[tid] = g_alpha[kk0 + tid];
    __syncthreads();

    int slice = g_topidx[j];
    const float4* base = (const float4*)hs
                       + (size_t)slice * (K_LEN * (H_DIM / 4))
                       + (size_t)kk0 * (H_DIM / 4);
    int t4 = tid & 63;
    int rg = tid >> 6;
    float4 acc = make_float4(0.f, 0.f, 0.f, 0.f);
    #pragma unroll 8
    for (int r = rg; r < 128; r += 4) {
        float a = sal[r];
        float4 vv = base[r * (H_DIM / 4) + t4];
        acc.x = fmaf(a, vv.x, acc.x); acc.y = fmaf(a, vv.y, acc.y);
        acc.z = fmaf(a, vv.z, acc.z); acc.w = fmaf(a, vv.w, acc.w);
    }
    sacc[tid] = acc;
    __syncthreads();
    if (tid < 64) {
        float4 a0 = sacc[tid], a1 = sacc[64 + tid];
        float4 a2 = sacc[128 + tid], a3 = sacc[192 + tid];
        float px = a0.x + a1.x + a2.x + a3.x;
        float py = a0.y + a1.y + a2.y + a3.y;
        float pz = a0.z + a1.z + a2.z + a3.z;
        float pw = a0.w + a1.w + a2.w + a3.w;
        // local score contribution: W_score[100 + 4*tid .. +3] . partial
        const float4 ws = *(const float4*)(W_score + TOPIC + tid * 4);
        float d = px * ws.x + py * ws.y + pz * ws.z + pw * ws.w;
        #pragma unroll
        for (int o = 16; o; o >>= 1) d += __shfl_xor_sync(0xffffffffu, d, o);
        if ((tid & 31) == 0) swsum[tid >> 5] = d;
    }
    __syncthreads();
    if (tid == 0) {
        atomicAdd(&g_score, g_beta[j] * (swsum[0] + swsum[1]));
    }
}

// ---------------- K5: GRU gates + h_new + predict_score ------------------
__global__ void k5_gru(const float* __restrict__ h0,
                       const float* __restrict__ b_ih,
                       const float* __restrict__ b_hh,
                       const float* __restrict__ W_score,
                       const float* __restrict__ b_score,
                       float* __restrict__ out) {
    int kk = blockIdx.x;
    int hh = threadIdx.x;
    float a = g_alpha[kk];
    const float* gh = g_gh + (size_t)kk * (3 * H_DIM);

    float gir = fmaf(a, g_u[hh],             b_ih[hh]);
    float giz = fmaf(a, g_u[H_DIM + hh],     b_ih[H_DIM + hh]);
    float gin = fmaf(a, g_u[2 * H_DIM + hh], b_ih[2 * H_DIM + hh]);
    float ghr = gh[hh]             + b_hh[hh];
    float ghz = gh[H_DIM + hh]     + b_hh[H_DIM + hh];
    float ghn = gh[2 * H_DIM + hh] + b_hh[2 * H_DIM + hh];

    float r = 1.f / (1.f + __expf(-(gir + ghr)));
    float z = 1.f / (1.f + __expf(-(giz + ghz)));
    float n = tanhf(gin + r * ghn);
    float h0v = h0[(size_t)kk * H_DIM + hh];
    out[1 + (size_t)kk * H_DIM + hh] = (1.f - z) * n + z * h0v;

    // predict_score = W_score[0:100].v + g_score + b_score
    if (kk == 0 && hh < 32) {
        float p = 0.f;
        for (int i = hh; i < TOPIC; i += 32) p += W_score[i] * g_v[i];
        #pragma unroll
        for (int o = 16; o; o >>= 1) p += __shfl_xor_sync(0xffffffffu, p, o);
        if (hh == 0) out[0] = p + g_score + b_score[0];
    }
}

// ---------------------------------------------------------------------------
extern "C" void kernel_launch(void* const* d_in, const int* in_sizes, int n_in,
                              void* d_out, int out_size) {
    const float* co_e     = (const float*)d_in[0];
    const float* ex_e     = (const float*)d_in[1];
    const float* s        = (const float*)d_in[2];
    const float* h        = (const float*)d_in[3];
    const float* vs       = (const float*)d_in[4];
    const float* hs       = (const float*)d_in[5];
    const float* W_resize = (const float*)d_in[6];
    const float* b_resize = (const float*)d_in[7];
    const float* Wk       = (const float*)d_in[8];
    const float* bk       = (const float*)d_in[9];
    const float* km       = (const float*)d_in[10];
    const float* W_score  = (const float*)d_in[11];
    const float* b_score  = (const float*)d_in[12];
    const float* W_ih     = (const float*)d_in[13];
    const float* W_hh     = (const float*)d_in[14];
    const float* b_ih     = (const float*)d_in[15];
    const float* b_hh     = (const float*)d_in[16];
    float* out = (float*)d_out;

    k1_embed    <<<21, 256>>>(W_resize, b_resize, ex_e, Wk, bk, co_e);
    k2_dots_gemm<<<DOT_BLOCKS + 96, 256>>>(vs, km, W_ih, s, h, W_hh);
    k3_select   <<<1, 1024>>>();
    k4_gather   <<<512, 256>>>(hs, W_score);
    k5_gru      <<<K_LEN, 256>>>(h, b_ih, b_hh, W_score, b_score, out);
}